// round 16
// baseline (speedup 1.0000x reference)
#include <cuda_runtime.h>
#include <cstdint>

typedef unsigned long long u64;

#define T_LEN 1024
#define BATCH 64
#define IDIM  128
#define HDIM  256
#define ODIM  128
#define G4    1024   // 4*HDIM
#define CLUS  8      // CTAs per cluster
#define BC    4      // batches per cluster  (16 clusters * 8 CTAs = 128 CTAs)

// ---------------- f32x2 helpers ----------------
__device__ __forceinline__ u64 fma2(u64 a, u64 b, u64 c) {
    u64 d;
    asm("fma.rn.f32x2 %0, %1, %2, %3;" : "=l"(d) : "l"(a), "l"(b), "l"(c));
    return d;
}
__device__ __forceinline__ u64 pk2(float x, float y) {
    u64 r;
    asm("mov.b64 %0, {%1, %2};" : "=l"(r) : "f"(x), "f"(y));
    return r;
}
__device__ __forceinline__ float2 up2(u64 v) {
    float2 f;
    asm("mov.b64 {%0, %1}, %2;" : "=f"(f.x), "=f"(f.y) : "l"(v));
    return f;
}
__device__ __forceinline__ float sigf(float x) {
    float e = __expf(-x);
    return __fdividef(1.0f, 1.0f + e);
}
// CTA-scope acquire wait on mbarrier parity (fast poll).
__device__ __forceinline__ void mbar_wait(unsigned mbar, unsigned parity) {
    asm volatile(
        "{\n\t"
        ".reg .pred P;\n\t"
        "WL_%=:\n\t"
        "mbarrier.try_wait.parity.acquire.cta.shared::cta.b64 P, [%0], %1;\n\t"
        "@!P bra WL_%=;\n\t"
        "}"
        :: "r"(mbar), "r"(parity) : "memory");
}
__device__ __forceinline__ void mbar_arm(unsigned mbar, unsigned tx) {
    asm volatile("mbarrier.arrive.expect_tx.shared.b64 _, [%0], %1;"
                 :: "r"(mbar), "r"(tx) : "memory");
}

// ---- dynamic smem layout (bytes) ----
#define OFF_HBUF    0u        // float [3][8][4][32]  12288  (h ring, slot = t%3)
#define OFF_HSTAGE  12288u    // float [2][4][32]      1024
#define OFF_PART    13312u    // float [128][20]      10240
#define OFF_WSOUT   23552u    // float [16][260]      16640
#define OFF_YPART   40192u    // float [16][4][5]      1280
#define OFF_XBUF    41472u    // u64   [2][4][64]      4096
#define OFF_GXBUF   45568u    // float [2][128][5]     5120
#define OFF_WIH2    50688u    // u64   [64][128]      65536
#define OFF_MBAR    116224u   // u64   [3]               24
#define SMEM_BYTES  116352u

// ---------------- THE kernel: fully fused LSTM + input GEMM + output GEMM ----
// 16 clusters x 8 CTAs. CTA rank owns hidden [rank*32,+32) -> 128 gate rows
// (W_hh in registers). h exchange: TRIPLE-buffered ring (slot t%3) + 3 mbars,
// each re-armed right after its wait -- removes the hbuf reuse race without
// putting any shadow work on the send's critical path.
__global__ void __launch_bounds__(512, 1) __cluster_dims__(CLUS, 1, 1)
k_rec(const float* __restrict__ xin,  const float* __restrict__ Wih,
      const float* __restrict__ Whh,  const float* __restrict__ bih,
      const float* __restrict__ bhh,  const float* __restrict__ Wout,
      const float* __restrict__ bout, float* __restrict__ y) {
    extern __shared__ __align__(16) char smraw[];
    float* hbuf   = (float*)(smraw + OFF_HBUF);    // [(slot*8+src)*4+b]*32+k
    float* hstage = (float*)(smraw + OFF_HSTAGE);  // [t&1][b][32]
    float* part   = (float*)(smraw + OFF_PART);    // [128][20]
    float* Wsout  = (float*)(smraw + OFF_WSOUT);   // [16][260]
    float* ypart  = (float*)(smraw + OFF_YPART);   // [16][4][5]
    u64*   xbuf   = (u64*)  (smraw + OFF_XBUF);    // [t&1][b][64] k-pairs
    float* gxbuf  = (float*)(smraw + OFF_GXBUF);   // [t&1][128][5]
    u64*   Wih2   = (u64*)  (smraw + OFF_WIH2);    // [kk][128 rows]
    u64*   mbar   = (u64*)  (smraw + OFF_MBAR);    // [3]

    int tid  = threadIdx.x;
    int rank = blockIdx.x & (CLUS - 1);
    int cid  = blockIdx.x >> 3;
    int j0   = rank * 32;
    int bg0  = cid * BC;

    int kq = tid >> 7;            // k-quarter 0..3
    int lr = tid & 127;           // gate row: g = lr>>5, jl = lr&31
    int g  = lr >> 5, jl = lr & 31;
    int gr = g * HDIM + j0 + jl;

    // W_hh slice -> registers as k-pairs
    u64 wreg[32];
    const u64* wrow = (const u64*)(Whh + (size_t)gr * HDIM) + kq * 32;
    #pragma unroll
    for (int i = 0; i < 32; i++) wreg[i] = wrow[i];

    // per-row combined bias (used by warps 4-11 in the x-matvec)
    float xbias = bih[gr] + bhh[gr];

    // W_out slice (rows rank*16..+16), padded rows 260
    {
        const float4* src = (const float4*)(Wout + (size_t)rank * 16 * HDIM);
        for (int i = tid; i < 16 * 64; i += 512) {
            int o = i >> 6, quad = i & 63;
            *(float4*)(Wsout + o * 260 + quad * 4) = src[o * 64 + quad];
        }
    }
    // W_ih slice as k-pairs [kk][r]
    for (int idx = tid; idx < 64 * 128; idx += 512) {
        int kk = idx >> 7, r = idx & 127;
        int grr = (r >> 5) * HDIM + j0 + (r & 31);
        Wih2[idx] = pk2(Wih[(size_t)grr * IDIM + 2 * kk],
                        Wih[(size_t)grr * IDIM + 2 * kk + 1]);
    }
    // zero hbuf (3 slots; slot 2 is h(-1) = 0 read at t=0)
    for (int idx = tid; idx < 3 * CLUS * BC * 32; idx += 512) hbuf[idx] = 0.f;

    unsigned mbar_a = (unsigned)__cvta_generic_to_shared(mbar);
    if (tid == 0) {
        #pragma unroll
        for (int i = 0; i < 3; i++) {
            asm volatile("mbarrier.init.shared.b64 [%0], 1;" :: "r"(mbar_a + i * 8u) : "memory");
            mbar_arm(mbar_a + i * 8u, 4096);   // pre-arm for uses t = 0,1,2
        }
    }

    // prologue: x(0), x(1) -> xbuf[0], xbuf[1]
    if (tid < 512) {
        int tt = tid >> 8, rem = tid & 255;
        int b = rem >> 6, kp = rem & 63;
        xbuf[tt * 256 + b * 64 + kp] =
            *(const u64*)(xin + ((size_t)(bg0 + b) * T_LEN + tt) * IDIM + 2 * kp);
    }
    __syncthreads();

    // x identities for warps 4-11
    int bh = (tid - 128) >> 7;   // valid for tid in [128,384)
    // prologue: gx(0) into gxbuf[0]
    if (tid >= 128 && tid < 384) {
        const u64* xb0 = xbuf + 0 * 256 + (2 * bh) * 64;
        const u64* xb1 = xb0 + 64;
        u64 a0 = 0, a1 = 0;
        #pragma unroll 8
        for (int kk = 0; kk < 64; kk++) {
            u64 w2 = Wih2[kk * 128 + lr];
            a0 = fma2(xb0[kk], w2, a0);
            a1 = fma2(xb1[kk], w2, a1);
        }
        float2 v0 = up2(a0), v1 = up2(a1);
        gxbuf[lr * 5 + 2 * bh]     = v0.x + v0.y + xbias;
        gxbuf[lr * 5 + 2 * bh + 1] = v1.x + v1.y + xbias;
    }

    // identities
    int ejl = tid >> 2, eb = tid & 3;            // epilogue (tid<128)
    float creg = 0.f;
    int yt = tid - 128;
    int yo = yt & 15, yb = (yt >> 4) & 3, yks = yt >> 6;  // y-dot (tid in [128,384))
    float ybias = 0.f;
    if (tid >= 128 && tid < 192) ybias = bout[rank * 16 + ((tid - 128) >> 2)];

    unsigned hbuf_a   = (unsigned)__cvta_generic_to_shared(hbuf);
    unsigned hstage_a = (unsigned)__cvta_generic_to_shared(hstage);

    __syncthreads();
    asm volatile("barrier.cluster.arrive.aligned;" ::: "memory");
    asm volatile("barrier.cluster.wait.aligned;"   ::: "memory");

    // h-ring state: ws = slot for h(t) (t%3), rs = slot for h(t-1); per-slot parity bits
    int ws = 0, rs = 2;
    unsigned parbits = 0;

    for (int t = 0; t < T_LEN; t++) {
        int q = t & 1, p = q ^ 1;   // 2-parities for hstage / xbuf / gxbuf

        // 1. LDG x(t+2) (warps 4-11; STS post-sync)
        u64 xr = 0;
        if (tid >= 128 && tid < 384 && t + 2 < T_LEN) {
            int e = tid - 128, b = e >> 6, kp = e & 63;
            xr = *(const u64*)(xin + ((size_t)(bg0 + b) * T_LEN + (t + 2)) * IDIM + 2 * kp);
        }

        // 2. wait for h(t-1) in slot rs, then re-arm that mbar for h(t+2).
        //    Re-arm ordering: h(t+2) deliveries require my h(t+1) send, which is
        //    after my step-(t+1) __syncthreads > this point.
        if (t > 0) {
            unsigned mba = mbar_a + (unsigned)rs * 8u;
            mbar_wait(mba, (parbits >> rs) & 1u);
            if (tid == 0) mbar_arm(mba, 4096);
            parbits ^= 1u << rs;
        }

        // 3. gate matvec (all warps): 1 gate row x 4 batches x 64 k
        const ulonglong2* hb = (const ulonglong2*)(hbuf + rs * CLUS * BC * 32);
        u64 a0 = 0, a1 = 0, a2 = 0, a3 = 0;
        #pragma unroll
        for (int i = 0; i < 16; i++) {
            int c  = 2 * kq + (i >> 3);
            int iv = i & 7;
            const ulonglong2* pc = hb + (size_t)(c * 4) * 8 + iv;
            ulonglong2 hv0 = pc[0];
            ulonglong2 hv1 = pc[8];
            ulonglong2 hv2 = pc[16];
            ulonglong2 hv3 = pc[24];
            u64 w0 = wreg[2 * i], w1 = wreg[2 * i + 1];
            a0 = fma2(w0, hv0.x, a0); a0 = fma2(w1, hv0.y, a0);
            a1 = fma2(w0, hv1.x, a1); a1 = fma2(w1, hv1.y, a1);
            a2 = fma2(w0, hv2.x, a2); a2 = fma2(w1, hv2.y, a2);
            a3 = fma2(w0, hv3.x, a3); a3 = fma2(w1, hv3.y, a3);
        }
        {
            float2 v;
            v = up2(a0); part[lr * 20 + 0 * 4 + kq] = v.x + v.y;
            v = up2(a1); part[lr * 20 + 1 * 4 + kq] = v.x + v.y;
            v = up2(a2); part[lr * 20 + 2 * 4 + kq] = v.x + v.y;
            v = up2(a3); part[lr * 20 + 3 * 4 + kq] = v.x + v.y;
        }
        __syncthreads();

        if (tid < 128) {
            // 4a. gate epilogue; gx from smem gxbuf[q]
            float4 p0 = *(const float4*)(part + (0 * 32 + ejl) * 20 + eb * 4);
            float4 p1 = *(const float4*)(part + (1 * 32 + ejl) * 20 + eb * 4);
            float4 p2 = *(const float4*)(part + (2 * 32 + ejl) * 20 + eb * 4);
            float4 p3 = *(const float4*)(part + (3 * 32 + ejl) * 20 + eb * 4);
            const float* gq = gxbuf + q * 640;
            float s0 = gq[(0 * 32 + ejl) * 5 + eb] + p0.x + p0.y + p0.z + p0.w;
            float s1 = gq[(1 * 32 + ejl) * 5 + eb] + p1.x + p1.y + p1.z + p1.w;
            float s2 = gq[(2 * 32 + ejl) * 5 + eb] + p2.x + p2.y + p2.z + p2.w;
            float s3 = gq[(3 * 32 + ejl) * 5 + eb] + p3.x + p3.y + p3.z + p3.w;

            float ig = sigf(s0);
            float fg = sigf(s1);
            float gg = 2.0f * sigf(2.0f * s2) - 1.0f;   // tanh
            float og = sigf(s3);
            creg = fg * creg + ig * gg;
            float h = og * (2.0f * sigf(2.0f * creg) - 1.0f);

            hstage[q * 128 + eb * 32 + ejl] = h;
            asm volatile("bar.sync 1, 128;" ::: "memory");   // send gated only by hstage

            if (tid == 0) {
                asm volatile("fence.proxy.async.shared::cta;" ::: "memory");
                unsigned src  = hstage_a + (unsigned)q * 512u;
                unsigned dstl = hbuf_a + (unsigned)ws * 4096u + (unsigned)rank * 512u;
                unsigned mb   = mbar_a + (unsigned)ws * 8u;
                #pragma unroll
                for (int r = 0; r < CLUS; r++) {
                    unsigned rd, rb;
                    asm("mapa.shared::cluster.u32 %0, %1, %2;" : "=r"(rd) : "r"(dstl), "r"(r));
                    asm("mapa.shared::cluster.u32 %0, %1, %2;" : "=r"(rb) : "r"(mb),   "r"(r));
                    asm volatile(
                        "cp.async.bulk.shared::cluster.shared::cta.mbarrier::complete_tx::bytes "
                        "[%0], [%1], 512, [%2];"
                        :: "r"(rd), "r"(src), "r"(rb) : "memory");
                }
            }
        } else if (tid < 384) {
            // 4b. shadow work (never gates the send; hbuf[rs] safe until h(t+2))
            if (t + 2 < T_LEN) {
                int e = tid - 128;
                xbuf[((t + 2) & 1) * 256 + (e >> 6) * 64 + (e & 63)] = xr;
            }
            // gx(t+1) = W_ih x(t+1) + bias -> gxbuf[p]
            {
                const u64* xb0 = xbuf + p * 256 + (2 * bh) * 64;
                const u64* xb1 = xb0 + 64;
                u64 c0 = 0, c1 = 0;
                #pragma unroll 8
                for (int kk = 0; kk < 64; kk++) {
                    u64 w2 = Wih2[kk * 128 + lr];
                    c0 = fma2(xb0[kk], w2, c0);
                    c1 = fma2(xb1[kk], w2, c1);
                }
                float2 v0 = up2(c0), v1 = up2(c1);
                gxbuf[p * 640 + lr * 5 + 2 * bh]     = v0.x + v0.y + xbias;
                gxbuf[p * 640 + lr * 5 + 2 * bh + 1] = v1.x + v1.y + xbias;
            }
            // y(t-1) partial dot from hbuf[rs]
            if (t > 0) {
                const ulonglong2* hq0 = (const ulonglong2*)
                    (hbuf + (rs * CLUS * BC + (2 * yks) * BC + yb) * 32);
                const ulonglong2* hq1 = (const ulonglong2*)
                    (hbuf + (rs * CLUS * BC + (2 * yks + 1) * BC + yb) * 32);
                const ulonglong2* wq  = (const ulonglong2*)(Wsout + yo * 260 + yks * 64);
                u64 ya = 0;
                #pragma unroll
                for (int i = 0; i < 8; i++) {
                    ulonglong2 hv = hq0[i];
                    ulonglong2 wv = wq[i];
                    ya = fma2(wv.x, hv.x, ya);
                    ya = fma2(wv.y, hv.y, ya);
                }
                #pragma unroll
                for (int i = 0; i < 8; i++) {
                    ulonglong2 hv = hq1[i];
                    ulonglong2 wv = wq[8 + i];
                    ya = fma2(wv.x, hv.x, ya);
                    ya = fma2(wv.y, hv.y, ya);
                }
                float2 v = up2(ya);
                ypart[(yo * 4 + yb) * 5 + yks] = v.x + v.y;
            }
            asm volatile("bar.sync 2, 256;" ::: "memory");   // warps 4-11 only
            if (tid < 192 && t > 0) {
                int o = (tid - 128) >> 2, b = (tid - 128) & 3;
                const float* yp = ypart + (o * 4 + b) * 5;
                float s = ybias + yp[0] + yp[1] + yp[2] + yp[3];
                y[((size_t)(bg0 + b) * T_LEN + (t - 1)) * ODIM + rank * 16 + o] = s;
            }
        }
        // warps 12-15: straight to next iteration

        // advance h-ring
        rs = ws;
        ws = (ws == 2) ? 0 : ws + 1;
    }

    // tail: wait h(1023) (slot rs, tracked parity), then y(1023)
    mbar_wait(mbar_a + (unsigned)rs * 8u, (parbits >> rs) & 1u);
    if (tid >= 128 && tid < 384) {
        const ulonglong2* hq0 = (const ulonglong2*)
            (hbuf + (rs * CLUS * BC + (2 * yks) * BC + yb) * 32);
        const ulonglong2* hq1 = (const ulonglong2*)
            (hbuf + (rs * CLUS * BC + (2 * yks + 1) * BC + yb) * 32);
        const ulonglong2* wq  = (const ulonglong2*)(Wsout + yo * 260 + yks * 64);
        u64 ya = 0;
        #pragma unroll
        for (int i = 0; i < 8; i++) {
            ulonglong2 hv = hq0[i];
            ulonglong2 wv = wq[i];
            ya = fma2(wv.x, hv.x, ya);
            ya = fma2(wv.y, hv.y, ya);
        }
        #pragma unroll
        for (int i = 0; i < 8; i++) {
            ulonglong2 hv = hq1[i];
            ulonglong2 wv = wq[8 + i];
            ya = fma2(wv.x, hv.x, ya);
            ya = fma2(wv.y, hv.y, ya);
        }
        float2 v = up2(ya);
        ypart[(yo * 4 + yb) * 5 + yks] = v.x + v.y;
    }
    __syncthreads();
    if (tid >= 128 && tid < 192) {
        int o = (tid - 128) >> 2, b = (tid - 128) & 3;
        const float* yp = ypart + (o * 4 + b) * 5;
        float s = ybias + yp[0] + yp[1] + yp[2] + yp[3];
        y[((size_t)(bg0 + b) * T_LEN + (T_LEN - 1)) * ODIM + rank * 16 + o] = s;
    }
}

// ---------------- launch: ONE kernel ----------------
extern "C" void kernel_launch(void* const* d_in, const int* in_sizes, int n_in,
                              void* d_out, int out_size) {
    const float* x    = (const float*)d_in[0];
    const float* Wih  = (const float*)d_in[1];
    const float* Whh  = (const float*)d_in[2];
    const float* bih  = (const float*)d_in[3];
    const float* bhh  = (const float*)d_in[4];
    const float* Wout = (const float*)d_in[5];
    const float* bout = (const float*)d_in[6];
    // d_in[7] = silence_mult (identity) -> no-op
    float* y = (float*)d_out;

    cudaFuncSetAttribute(k_rec, cudaFuncAttributeMaxDynamicSharedMemorySize, SMEM_BYTES);
    k_rec<<<128, 512, SMEM_BYTES>>>(x, Wih, Whh, bih, bhh, Wout, bout, y);
}

// round 17
// speedup vs baseline: 1.1004x; 1.1004x over previous
#include <cuda_runtime.h>
#include <cstdint>

typedef unsigned long long u64;

#define T_LEN 1024
#define BATCH 64
#define IDIM  128
#define HDIM  256
#define ODIM  128
#define G4    1024   // 4*HDIM
#define CLUS  8      // CTAs per cluster
#define BC    4      // batches per cluster  (16 clusters * 8 CTAs = 128 CTAs)

// ---------------- scratch (device globals; no runtime allocation) ----------------
__device__ float g_Gx[(size_t)T_LEN * G4 * BATCH];     // [t][r][b]  r = gate*256 + j
__device__ float g_xT[(size_t)T_LEN * IDIM * BATCH];   // [t][k][b]
__device__ float g_WihT [IDIM * G4];                   // [k][r]

// ---------------- f32x2 helpers ----------------
__device__ __forceinline__ u64 fma2(u64 a, u64 b, u64 c) {
    u64 d;
    asm("fma.rn.f32x2 %0, %1, %2, %3;" : "=l"(d) : "l"(a), "l"(b), "l"(c));
    return d;
}
__device__ __forceinline__ u64 pk2(float x, float y) {
    u64 r;
    asm("mov.b64 %0, {%1, %2};" : "=l"(r) : "f"(x), "f"(y));
    return r;
}
__device__ __forceinline__ float2 up2(u64 v) {
    float2 f;
    asm("mov.b64 {%0, %1}, %2;" : "=f"(f.x), "=f"(f.y) : "l"(v));
    return f;
}
__device__ __forceinline__ float sigf(float x) {
    float e = __expf(-x);
    return __fdividef(1.0f, 1.0f + e);
}
// CTA-scope acquire wait on mbarrier parity (fast poll).
__device__ __forceinline__ void mbar_wait(unsigned mbar, unsigned parity) {
    asm volatile(
        "{\n\t"
        ".reg .pred P;\n\t"
        "WL_%=:\n\t"
        "mbarrier.try_wait.parity.acquire.cta.shared::cta.b64 P, [%0], %1;\n\t"
        "@!P bra WL_%=;\n\t"
        "}"
        :: "r"(mbar), "r"(parity) : "memory");
}
__device__ __forceinline__ void mbar_arm(unsigned mbar, unsigned tx) {
    asm volatile("mbarrier.arrive.expect_tx.shared.b64 _, [%0], %1;"
                 :: "r"(mbar), "r"(tx) : "memory");
}

// ---------------- prep: transpose W_ih ----------------
__global__ void k_prepw(const float* __restrict__ Wih) {
    int i = blockIdx.x * 256 + threadIdx.x;
    if (i < G4 * IDIM) { int r = i >> 7; int k = i & 127; g_WihT[k * G4 + r] = Wih[i]; }
}

// ---------------- prep: transpose x -> [t][k][b] ----------------
__global__ void __launch_bounds__(256) k_prepx(const float* __restrict__ x) {
    __shared__ float s[64][129];
    int t = blockIdx.x, tid = threadIdx.x;
    for (int idx = tid; idx < 64 * 128; idx += 256) {
        int b = idx >> 7, k = idx & 127;
        s[b][k] = x[((size_t)b * T_LEN + t) * IDIM + k];
    }
    __syncthreads();
    float* xo = g_xT + (size_t)t * IDIM * BATCH;
    for (int idx = tid; idx < IDIM * 64; idx += 256) {
        int k = idx >> 6, b = idx & 63;
        xo[idx] = s[b][k];
    }
}

// ---------------- kernel 1: Gx = x@W_ih^T + bias, 64-row tiles (2 CTAs/SM) ----
__global__ void __launch_bounds__(256) k_gx(const float* __restrict__ bih,
                                            const float* __restrict__ bhh) {
    extern __shared__ float sm[];
    float* Wt = sm;                        // [128k][64r]   32KB
    u64*  Xd  = (u64*)(sm + 128 * 64);     // [128k][64b] dup  64KB
    int tid = threadIdx.x;
    int r0 = blockIdx.x * 64;
    int t  = blockIdx.y;

    // vectorized fills
    {
        const float4* src = (const float4*)(g_WihT + r0);   // row k at k*(G4/4)
        float4* dst = (float4*)Wt;
        for (int i4 = tid; i4 < 128 * 16; i4 += 256) {
            int k = i4 >> 4, rq = i4 & 15;
            dst[i4] = src[k * (G4 / 4) + rq];
        }
        const float4* xt4 = (const float4*)(g_xT + (size_t)t * IDIM * BATCH);
        for (int i4 = tid; i4 < 128 * 16; i4 += 256) {
            float4 v = xt4[i4];
            u64* o = Xd + i4 * 4;
            o[0] = pk2(v.x, v.x); o[1] = pk2(v.y, v.y);
            o[2] = pk2(v.z, v.z); o[3] = pk2(v.w, v.w);
        }
    }
    __syncthreads();

    int rg = tid >> 4, bg = tid & 15;   // rows rg*4..+4 (2 pairs), b bg*4..+4
    u64 acc[2][4];
    #pragma unroll
    for (int p = 0; p < 2; p++)
        #pragma unroll
        for (int q = 0; q < 4; q++) acc[p][q] = 0ull;

    #pragma unroll 4
    for (int k = 0; k < 128; k++) {
        const u64* wp = (const u64*)(Wt + k * 64 + rg * 4);
        const u64* xp = Xd + k * 64 + bg * 4;
        u64 w0 = wp[0], w1 = wp[1];
        u64 x0 = xp[0], x1 = xp[1], x2 = xp[2], x3 = xp[3];
        acc[0][0] = fma2(w0, x0, acc[0][0]);
        acc[0][1] = fma2(w0, x1, acc[0][1]);
        acc[0][2] = fma2(w0, x2, acc[0][2]);
        acc[0][3] = fma2(w0, x3, acc[0][3]);
        acc[1][0] = fma2(w1, x0, acc[1][0]);
        acc[1][1] = fma2(w1, x1, acc[1][1]);
        acc[1][2] = fma2(w1, x2, acc[1][2]);
        acc[1][3] = fma2(w1, x3, acc[1][3]);
    }

    float* gout = g_Gx + (size_t)t * G4 * BATCH;
    #pragma unroll
    for (int p = 0; p < 2; p++) {
        int r = r0 + rg * 4 + 2 * p;
        float bia = bih[r] + bhh[r];
        float bib = bih[r + 1] + bhh[r + 1];
        #pragma unroll
        for (int q = 0; q < 4; q++) {
            float2 v = up2(acc[p][q]);
            int b = bg * 4 + q;
            gout[(size_t)r * BATCH + b]       = v.x + bia;
            gout[(size_t)(r + 1) * BATCH + b] = v.y + bib;
        }
    }
}

// ---------------- kernel 2: clustered recurrence + fused y GEMM --------------
// R16's race-free triple-buffered h-ring (3 slots + 3 mbars, re-arm after wait)
// WITHOUT the in-loop x-GEMM (Gx precomputed, register-pipelined one step).
// Warps 0-3: gate epilogue + send (narrow bar.sync 1,128).
// Warps 4-11: y(t-1) dot post-sync (cheap, hides in slack). Warps 12-15: free.
__global__ void __launch_bounds__(512, 1) __cluster_dims__(CLUS, 1, 1)
k_rec(const float* __restrict__ Whh, const float* __restrict__ Wout,
      const float* __restrict__ bout, float* __restrict__ y) {
    __shared__ __align__(16) float hbuf[3][CLUS][BC][32];  // 12KB, slot = t%3
    __shared__ __align__(16) float hstage[2][BC][32];      // 1KB
    __shared__ __align__(16) float part[128][20];
    __shared__ __align__(16) float Wsout[16][260];         // padded
    __shared__ __align__(16) float ypart[16][4][5];        // padded
    __shared__ u64 mbar[3];

    int tid  = threadIdx.x;
    int rank = blockIdx.x & (CLUS - 1);
    int cid  = blockIdx.x >> 3;
    int j0   = rank * 32;
    int bg0  = cid * BC;

    int kq = tid >> 7;            // k-quarter 0..3
    int lr = tid & 127;           // gate row: g = lr>>5, jl = lr&31
    int g  = lr >> 5, jl = lr & 31;
    int gr = g * HDIM + j0 + jl;

    // W_hh slice -> registers as k-pairs
    u64 wreg[32];
    const u64* wrow = (const u64*)(Whh + (size_t)gr * HDIM) + kq * 32;
    #pragma unroll
    for (int i = 0; i < 32; i++) wreg[i] = wrow[i];

    // W_out slice (rows rank*16..+16), padded rows 260
    {
        const float4* src = (const float4*)(Wout + (size_t)rank * 16 * HDIM);
        for (int i = tid; i < 16 * 64; i += 512) {
            int o = i >> 6, quad = i & 63;
            *(float4*)(&Wsout[o][0] + quad * 4) = src[o * 64 + quad];
        }
    }
    // zero hbuf (slot 2 = h(-1) = 0, read at t=0)
    for (int idx = tid; idx < 3 * CLUS * BC * 32; idx += 512) ((float*)hbuf)[idx] = 0.f;

    unsigned mbar_a = (unsigned)__cvta_generic_to_shared(&mbar[0]);
    if (tid == 0) {
        #pragma unroll
        for (int i = 0; i < 3; i++) {
            asm volatile("mbarrier.init.shared.b64 [%0], 1;" :: "r"(mbar_a + i * 8u) : "memory");
            mbar_arm(mbar_a + i * 8u, 4096);
        }
    }

    // identities
    int ejl = tid >> 2, eb = tid & 3;            // epilogue (tid<128)
    float creg = 0.f;
    int yt = tid - 128;
    int yo = yt & 15, yb = (yt >> 4) & 3, yks = yt >> 6;  // y-dot (tid in [128,384))
    float ybias = 0.f;
    if (tid >= 128 && tid < 192) ybias = bout[rank * 16 + ((tid - 128) >> 2)];

    unsigned hbuf_a   = (unsigned)__cvta_generic_to_shared(&hbuf[0][0][0][0]);
    unsigned hstage_a = (unsigned)__cvta_generic_to_shared(&hstage[0][0][0]);

    // Gx register pipeline: gxn holds Gx(t) at entry to iteration t
    const float* gbase = g_Gx + (size_t)(j0 + ejl) * BATCH + (bg0 + eb);
    float gxn0 = 0.f, gxn1 = 0.f, gxn2 = 0.f, gxn3 = 0.f;
    if (tid < 128) {
        gxn0 = gbase[0];
        gxn1 = gbase[1 * HDIM * BATCH];
        gxn2 = gbase[2 * HDIM * BATCH];
        gxn3 = gbase[3 * HDIM * BATCH];
    }

    __syncthreads();
    asm volatile("barrier.cluster.arrive.aligned;" ::: "memory");
    asm volatile("barrier.cluster.wait.aligned;"   ::: "memory");

    // h-ring state: ws = slot for h(t), rs = slot for h(t-1); per-slot parity
    int ws = 0, rs = 2;
    unsigned parbits = 0;

    for (int t = 0; t < T_LEN; t++) {
        int q = t & 1;

        // 1. consume pipelined Gx(t); issue loads for Gx(t+1)
        float gx0 = gxn0, gx1 = gxn1, gx2 = gxn2, gx3 = gxn3;
        if (tid < 128 && t + 1 < T_LEN) {
            const float* gp = gbase + (size_t)(t + 1) * G4 * BATCH;
            gxn0 = gp[0];
            gxn1 = gp[1 * HDIM * BATCH];
            gxn2 = gp[2 * HDIM * BATCH];
            gxn3 = gp[3 * HDIM * BATCH];
        }

        // 2. wait for h(t-1) in slot rs, re-arm for h(t+2)
        //    (safe: h(t+2) deliveries require my h(t+1) send > my step-(t+1) sync)
        if (t > 0) {
            unsigned mba = mbar_a + (unsigned)rs * 8u;
            mbar_wait(mba, (parbits >> rs) & 1u);
            if (tid == 0) mbar_arm(mba, 4096);
            parbits ^= 1u << rs;
        }

        // 3. gate matvec (all warps): 1 gate row x 4 batches x 64 k
        const ulonglong2* hb = (const ulonglong2*)(hbuf[rs]);
        u64 a0 = 0, a1 = 0, a2 = 0, a3 = 0;
        #pragma unroll
        for (int i = 0; i < 16; i++) {
            int c  = 2 * kq + (i >> 3);
            int iv = i & 7;
            const ulonglong2* pc = hb + (size_t)(c * 4) * 8 + iv;
            ulonglong2 hv0 = pc[0];
            ulonglong2 hv1 = pc[8];
            ulonglong2 hv2 = pc[16];
            ulonglong2 hv3 = pc[24];
            u64 w0 = wreg[2 * i], w1 = wreg[2 * i + 1];
            a0 = fma2(w0, hv0.x, a0); a0 = fma2(w1, hv0.y, a0);
            a1 = fma2(w0, hv1.x, a1); a1 = fma2(w1, hv1.y, a1);
            a2 = fma2(w0, hv2.x, a2); a2 = fma2(w1, hv2.y, a2);
            a3 = fma2(w0, hv3.x, a3); a3 = fma2(w1, hv3.y, a3);
        }
        {
            float2 v;
            v = up2(a0); part[lr][0 * 4 + kq] = v.x + v.y;
            v = up2(a1); part[lr][1 * 4 + kq] = v.x + v.y;
            v = up2(a2); part[lr][2 * 4 + kq] = v.x + v.y;
            v = up2(a3); part[lr][3 * 4 + kq] = v.x + v.y;
        }
        __syncthreads();

        if (tid < 128) {
            // 4a. gate epilogue -> h -> narrow-gated send
            float4 p0 = *(const float4*)&part[0 * 32 + ejl][eb * 4];
            float4 p1 = *(const float4*)&part[1 * 32 + ejl][eb * 4];
            float4 p2 = *(const float4*)&part[2 * 32 + ejl][eb * 4];
            float4 p3 = *(const float4*)&part[3 * 32 + ejl][eb * 4];
            float s0 = gx0 + p0.x + p0.y + p0.z + p0.w;
            float s1 = gx1 + p1.x + p1.y + p1.z + p1.w;
            float s2 = gx2 + p2.x + p2.y + p2.z + p2.w;
            float s3 = gx3 + p3.x + p3.y + p3.z + p3.w;

            float ig = sigf(s0);
            float fg = sigf(s1);
            float gg = 2.0f * sigf(2.0f * s2) - 1.0f;   // tanh
            float og = sigf(s3);
            creg = fg * creg + ig * gg;
            float h = og * (2.0f * sigf(2.0f * creg) - 1.0f);

            hstage[q][eb][ejl] = h;
            asm volatile("bar.sync 1, 128;" ::: "memory");

            if (tid == 0) {
                asm volatile("fence.proxy.async.shared::cta;" ::: "memory");
                unsigned src  = hstage_a + (unsigned)q * 512u;
                unsigned dstl = hbuf_a + (unsigned)ws * 4096u + (unsigned)rank * 512u;
                unsigned mb   = mbar_a + (unsigned)ws * 8u;
                #pragma unroll
                for (int r = 0; r < CLUS; r++) {
                    unsigned rd, rb;
                    asm("mapa.shared::cluster.u32 %0, %1, %2;" : "=r"(rd) : "r"(dstl), "r"(r));
                    asm("mapa.shared::cluster.u32 %0, %1, %2;" : "=r"(rb) : "r"(mb),   "r"(r));
                    asm volatile(
                        "cp.async.bulk.shared::cluster.shared::cta.mbarrier::complete_tx::bytes "
                        "[%0], [%1], 512, [%2];"
                        :: "r"(rd), "r"(src), "r"(rb) : "memory");
                }
            }
        } else if (tid < 384) {
            // 4b. y(t-1) dot from hbuf[rs] (slot safe until h(t+2))
            if (t > 0) {
                const ulonglong2* hq0 = (const ulonglong2*)(&hbuf[rs][2 * yks][yb][0]);
                const ulonglong2* hq1 = (const ulonglong2*)(&hbuf[rs][2 * yks + 1][yb][0]);
                const ulonglong2* wq  = (const ulonglong2*)(&Wsout[yo][0] + yks * 64);
                u64 ya = 0;
                #pragma unroll
                for (int i = 0; i < 8; i++) {
                    ulonglong2 hv = hq0[i];
                    ulonglong2 wv = wq[i];
                    ya = fma2(wv.x, hv.x, ya);
                    ya = fma2(wv.y, hv.y, ya);
                }
                #pragma unroll
                for (int i = 0; i < 8; i++) {
                    ulonglong2 hv = hq1[i];
                    ulonglong2 wv = wq[8 + i];
                    ya = fma2(wv.x, hv.x, ya);
                    ya = fma2(wv.y, hv.y, ya);
                }
                float2 v = up2(ya);
                ypart[yo][yb][yks] = v.x + v.y;
            }
            asm volatile("bar.sync 2, 256;" ::: "memory");
            if (tid < 192 && t > 0) {
                int o = (tid - 128) >> 2, b = (tid - 128) & 3;
                const float* yp = &ypart[o][b][0];
                float s = ybias + yp[0] + yp[1] + yp[2] + yp[3];
                y[((size_t)(bg0 + b) * T_LEN + (t - 1)) * ODIM + rank * 16 + o] = s;
            }
        }
        // warps 12-15: straight to next iteration

        rs = ws;
        ws = (ws == 2) ? 0 : ws + 1;
    }

    // tail: wait h(1023), compute & store y(1023)
    mbar_wait(mbar_a + (unsigned)rs * 8u, (parbits >> rs) & 1u);
    if (tid >= 128 && tid < 384) {
        const ulonglong2* hq0 = (const ulonglong2*)(&hbuf[rs][2 * yks][yb][0]);
        const ulonglong2* hq1 = (const ulonglong2*)(&hbuf[rs][2 * yks + 1][yb][0]);
        const ulonglong2* wq  = (const ulonglong2*)(&Wsout[yo][0] + yks * 64);
        u64 ya = 0;
        #pragma unroll
        for (int i = 0; i < 8; i++) {
            ulonglong2 hv = hq0[i];
            ulonglong2 wv = wq[i];
            ya = fma2(wv.x, hv.x, ya);
            ya = fma2(wv.y, hv.y, ya);
        }
        #pragma unroll
        for (int i = 0; i < 8; i++) {
            ulonglong2 hv = hq1[i];
            ulonglong2 wv = wq[8 + i];
            ya = fma2(wv.x, hv.x, ya);
            ya = fma2(wv.y, hv.y, ya);
        }
        float2 v = up2(ya);
        ypart[yo][yb][yks] = v.x + v.y;
    }
    __syncthreads();
    if (tid >= 128 && tid < 192) {
        int o = (tid - 128) >> 2, b = (tid - 128) & 3;
        const float* yp = &ypart[o][b][0];
        float s = ybias + yp[0] + yp[1] + yp[2] + yp[3];
        y[((size_t)(bg0 + b) * T_LEN + (T_LEN - 1)) * ODIM + rank * 16 + o] = s;
    }
}

// ---------------- launch ----------------
extern "C" void kernel_launch(void* const* d_in, const int* in_sizes, int n_in,
                              void* d_out, int out_size) {
    const float* x    = (const float*)d_in[0];
    const float* Wih  = (const float*)d_in[1];
    const float* Whh  = (const float*)d_in[2];
    const float* bih  = (const float*)d_in[3];
    const float* bhh  = (const float*)d_in[4];
    const float* Wout = (const float*)d_in[5];
    const float* bout = (const float*)d_in[6];
    // d_in[7] = silence_mult (identity) -> no-op
    float* y = (float*)d_out;

    cudaFuncSetAttribute(k_gx, cudaFuncAttributeMaxDynamicSharedMemorySize, 98304);

    k_prepw<<<512, 256>>>(Wih);
    k_prepx<<<1024, 256>>>(x);
    k_gx<<<dim3(16, 1024), 256, 98304>>>(bih, bhh);
    k_rec<<<128, 512>>>(Whh, Wout, bout, y);
}